// round 7
// baseline (speedup 1.0000x reference)
#include <cuda_runtime.h>
#include <cuda_bf16.h>
#include <cstdint>
#include <math.h>

// ---------------- problem constants ----------------
#define Dv      64
#define HWv     1024
#define NROWS   32768
#define Kv      1024
#define EPSV        1e-12f
#define PERP_EPSV   1e-10f

#define M_TILE   256                 // rows per CTA
#define THREADS  512                 // 16 warps: 2 codebook-halves x 8 row-warps
#define GRID     (NROWS / M_TILE)    // 128 CTAs -> single wave

// ---------------- SMEM layout (byte offsets into dynamic smem) ----------------
#define A_OFF    0                   // 256 x 64 bf16 (swizzled 128B rows) = 32KB
#define B_OFF    32768               // 1024 x 64 bf16 = 128KB
#define CN_OFF   163840              // 1024 fp32 norms = 4KB
#define BST_OFF  167936              // 2 x 256 fp32 best-dist
#define IDX_OFF  169984              // 2 x 256 int  best-idx
#define SMEM_DYN 172032

// ---------------- device scratch ----------------
__device__ __align__(16) float        g_cnorm[Kv];
__device__ unsigned int               g_counts[Kv];
__device__ unsigned int               g_ticket;
// codebook as bf16, PRE-SWIZZLED (16B-unit XOR by (row&7)<<4): linear cp.async.
__device__ __align__(16) unsigned char g_cb[Kv * Dv * 2];

// ---------------- helpers ----------------
__device__ __forceinline__ uint32_t smem_u32(const void* p) {
    uint32_t a;
    asm("{ .reg .u64 t; cvta.to.shared.u64 t, %1; cvt.u32.u64 %0, t; }"
        : "=r"(a) : "l"(p));
    return a;
}
#define SWZ(row, unit) ((((uint32_t)(row) * 128u) + (uint32_t)(unit) * 16u) ^ ((((uint32_t)(row)) & 7u) << 4))

__device__ __forceinline__ void ldsm4(uint32_t addr, uint32_t& r0, uint32_t& r1,
                                      uint32_t& r2, uint32_t& r3) {
    asm volatile("ldmatrix.sync.aligned.m8n8.x4.shared.b16 {%0,%1,%2,%3}, [%4];"
                 : "=r"(r0), "=r"(r1), "=r"(r2), "=r"(r3) : "r"(addr));
}
__device__ __forceinline__ void mma_bf16(float* d, const uint32_t* a, const uint32_t* b) {
    asm volatile(
        "mma.sync.aligned.m16n8k16.row.col.f32.bf16.bf16.f32 "
        "{%0,%1,%2,%3}, {%4,%5,%6,%7}, {%8,%9}, {%0,%1,%2,%3};"
        : "+f"(d[0]), "+f"(d[1]), "+f"(d[2]), "+f"(d[3])
        : "r"(a[0]), "r"(a[1]), "r"(a[2]), "r"(a[3]), "r"(b[0]), "r"(b[1]));
}
__device__ __forceinline__ void cp16(uint32_t saddr, const void* g) {
    asm volatile("cp.async.cg.shared.global [%0], [%1], 16;" :: "r"(saddr), "l"(g));
}
#define CP_COMMIT() asm volatile("cp.async.commit_group;" ::: "memory")
#define CP_WAIT0()  asm volatile("cp.async.wait_group 0;"  ::: "memory")

// ---------------------------------------------------------------------------
// prep: codebook bf16 convert (pre-swizzled) + exact fp32 norms + zero
// histogram + reset ticket. thread t -> (codebook k = t>>3, 16B-unit u = t&7).
// ---------------------------------------------------------------------------
__global__ void nsvq_prep_kernel(const float* __restrict__ cb) {
    const int t = blockIdx.x * blockDim.x + threadIdx.x;   // Kv*8 = 8192 threads
    const int k = t >> 3, u = t & 7;
    const float4* src = reinterpret_cast<const float4*>(cb + k * Dv + u * 8);
    float4 a = src[0], b = src[1];
    float v[8] = {a.x, a.y, a.z, a.w, b.x, b.y, b.z, b.w};

    float part = 0.f;
    unsigned short hs[8];
    #pragma unroll
    for (int i = 0; i < 8; i++) {
        part = fmaf(v[i], v[i], part);
        hs[i] = __bfloat16_as_ushort(__float2bfloat16(v[i]));
    }
    part += __shfl_xor_sync(0xffffffffu, part, 1);
    part += __shfl_xor_sync(0xffffffffu, part, 2);
    part += __shfl_xor_sync(0xffffffffu, part, 4);
    if (u == 0) g_cnorm[k] = part;

    uint4 ho;
    ho.x = (uint32_t)hs[0] | ((uint32_t)hs[1] << 16);
    ho.y = (uint32_t)hs[2] | ((uint32_t)hs[3] << 16);
    ho.z = (uint32_t)hs[4] | ((uint32_t)hs[5] << 16);
    ho.w = (uint32_t)hs[6] | ((uint32_t)hs[7] << 16);
    *reinterpret_cast<uint4*>(g_cb + SWZ(k, u)) = ho;

    if (t < Kv)  g_counts[t] = 0u;
    if (t == 0)  g_ticket = 0u;
}

// ---------------------------------------------------------------------------
// main: bf16 HMMA distance GEMM, split-K over codebook halves (16 warps),
// fused argmin merge + exact fp32 NSVQ epilogue (2 threads/row) + perplexity.
// ---------------------------------------------------------------------------
__global__ __launch_bounds__(THREADS, 1)
void nsvq_hmma_kernel(const float* __restrict__ inputs,
                      const float* __restrict__ cbf,
                      const float* __restrict__ noise,
                      float*       __restrict__ out)
{
    extern __shared__ char sp[];
    const uint32_t sbase = smem_u32(sp);

    const int tid   = threadIdx.x;
    const int wid   = tid >> 5;
    const int lane  = tid & 31;
    const int wslot = wid & 7;         // row-warp (32 rows)
    const int half  = wid >> 3;        // codebook half (0: k<512, 1: k>=512)

    // epilogue split: 2 threads per row
    const int erow = tid >> 1;                       // row in tile
    const int epar = tid & 1;                        // which 32-dim half
    const int en   = blockIdx.x * M_TILE + erow;     // global row
    const int ebb  = en >> 10;
    const int ehw  = en & 1023;
    const float* exin = inputs + (size_t)ebb * (Dv * HWv) + ehw;

    // ---- async copy: whole codebook + norms ----
    {
        const char* gb = (const char*)g_cb;
        #pragma unroll
        for (int i = 0; i < 16; i++) {               // 512 thr x 16 x 16B = 128KB
            uint32_t o = ((uint32_t)tid + (uint32_t)i * 512u) * 16u;
            cp16(sbase + B_OFF + o, gb + o);
        }
        if (tid < 256)
            cp16(sbase + CN_OFF + (uint32_t)tid * 16u,
                 (const char*)g_cnorm + (size_t)tid * 16);
        CP_COMMIT();
    }

    // ---- load x half-row, convert to bf16 into SMEM A (swizzled) ----
    {
        #pragma unroll
        for (int i = 0; i < 16; i++) {               // 16 bf16x2 words = 32 dims
            int d0 = epar * 32 + 2 * i;
            float xl = exin[(size_t)d0 * HWv];
            float xh = exin[(size_t)(d0 + 1) * HWv];
            uint32_t off = SWZ(erow, epar * 4 + (i >> 2)) + (uint32_t)(i & 3) * 4u;
            unsigned short h0 = __bfloat16_as_ushort(__float2bfloat16(xl));
            unsigned short h1 = __bfloat16_as_ushort(__float2bfloat16(xh));
            *reinterpret_cast<uint32_t*>(sp + A_OFF + off) = (uint32_t)h0 | ((uint32_t)h1 << 16);
        }
    }

    CP_WAIT0();
    __syncthreads();   // A + B + cn visible to all warps

    // ---- load A fragments (32 rows per row-warp; both halves load same) ----
    uint32_t ah[2][4][4];
    {
        const int arow = wslot * 32 + (lane & 7) + ((lane >> 3) & 1) * 8;
        const int aun  = (lane >> 4);
        #pragma unroll
        for (int mt = 0; mt < 2; mt++)
            #pragma unroll
            for (int kc = 0; kc < 4; kc++) {
                uint32_t ad = sbase + A_OFF + (uint32_t)SWZ(arow + mt * 16, kc * 2 + aun);
                ldsm4(ad, ah[mt][kc][0], ah[mt][kc][1], ah[mt][kc][2], ah[mt][kc][3]);
            }
    }

    float best[4] = {3.402823466e38f, 3.402823466e38f, 3.402823466e38f, 3.402823466e38f};
    int   bidx[4] = {0, 0, 0, 0};

    const int browq = (lane & 7) + ((lane >> 4) & 1) * 8;   // B ldmatrix row within n16
    const int bunq  = (lane >> 3) & 1;                       // B k-unit parity
    const float* cn = reinterpret_cast<const float*>(sp + CN_OFF);

    // strength-reduced swizzled B base: groups step 16 rows (= 0 mod 8), so the
    // XOR term ((row&7)<<4) is constant across g; units occupy bits [4:7).
    const uint32_t xorv = ((uint32_t)(browq & 7)) << 4;
    uint32_t bbase = sbase + B_OFF + (uint32_t)(half * 512 + browq) * 128u;
    uint32_t ukc[4];
    #pragma unroll
    for (int kc = 0; kc < 4; kc++)
        ukc[kc] = (((uint32_t)(kc * 2 + bunq)) * 16u) ^ xorv;

    #pragma unroll 2
    for (int g = 0; g < 32; g++) {                    // 32 n-groups of 16 per half
        float acc[2][2][4];
        #pragma unroll
        for (int mt = 0; mt < 2; mt++)
            #pragma unroll
            for (int nt = 0; nt < 2; nt++)
                #pragma unroll
                for (int j = 0; j < 4; j++) acc[mt][nt][j] = 0.f;

        #pragma unroll
        for (int kc = 0; kc < 4; kc++) {
            uint32_t bh[4];
            ldsm4(bbase + ukc[kc], bh[0], bh[1], bh[2], bh[3]);
            #pragma unroll
            for (int mt = 0; mt < 2; mt++) {
                mma_bf16(acc[mt][0], ah[mt][kc], bh + 0);
                mma_bf16(acc[mt][1], ah[mt][kc], bh + 2);
            }
        }
        bbase += 16u * 128u;

        const int cb0 = half * 512 + g * 16 + 2 * (lane & 3);
        float cnl[4];
        {
            float2 p0 = *reinterpret_cast<const float2*>(cn + cb0);
            float2 p1 = *reinterpret_cast<const float2*>(cn + cb0 + 8);
            cnl[0] = p0.x; cnl[1] = p0.y; cnl[2] = p1.x; cnl[3] = p1.y;
        }
        #pragma unroll
        for (int mt = 0; mt < 2; mt++)
            #pragma unroll
            for (int nt = 0; nt < 2; nt++)
                #pragma unroll
                for (int j = 0; j < 4; j++) {
                    float dist = fmaf(-2.f, acc[mt][nt][j], cnl[nt * 2 + (j & 1)]);
                    int   kk   = cb0 + nt * 8 + (j & 1);
                    int   s    = mt * 2 + (j >> 1);
                    if (dist < best[s]) { best[s] = dist; bidx[s] = kk; }
                }
    }

    // ---- quad butterfly reduce (lanes sharing the same rows) ----
    #pragma unroll
    for (int s = 0; s < 4; s++) {
        #pragma unroll
        for (int d = 1; d <= 2; d <<= 1) {
            float od = __shfl_xor_sync(0xffffffffu, best[s], d);
            int   oi = __shfl_xor_sync(0xffffffffu, bidx[s], d);
            if (od < best[s] || (od == best[s] && oi < bidx[s])) { best[s] = od; bidx[s] = oi; }
        }
    }
    // lane writes row = wslot*32 + lane/4 + (lane%4)*8, per codebook half
    {
        float* sbst = reinterpret_cast<float*>(sp + BST_OFF) + half * 256;
        int*   sidx = reinterpret_cast<int*>(sp + IDX_OFF)  + half * 256;
        int r = wslot * 32 + (lane >> 2) + (lane & 3) * 8;
        sbst[r] = best[lane & 3];
        sidx[r] = bidx[lane & 3];
    }
    __syncthreads();

    // ---- merge halves (half-0 indices < half-1, so tie -> half 0 = jnp rule)
    int myidx;
    {
        const float* sbst = reinterpret_cast<const float*>(sp + BST_OFF);
        const int*   sidx = reinterpret_cast<const int*>(sp + IDX_OFF);
        float d0 = sbst[erow], d1 = sbst[256 + erow];
        myidx = (d1 < d0) ? sidx[256 + erow] : sidx[erow];
    }

    // ---- exact fp32 NSVQ epilogue: 2 threads/row, 32 dims each ----
    const float4* cbest4 = reinterpret_cast<const float4*>(cbf + (size_t)myidx * Dv) + epar * 8;
    const float4* nr4    = reinterpret_cast<const float4*>(noise + (size_t)en * Dv) + epar * 8;

    float xl[32];
    float nb = 0.f, nn = 0.f;
    float nz[32];
    #pragma unroll
    for (int i = 0; i < 8; i++) {
        float4 cv = cbest4[i];
        float4 nv = nr4[i];
        #pragma unroll
        for (int j = 0; j < 4; j++) {
            int ii = 4 * i + j;
            xl[ii] = exin[(size_t)(epar * 32 + ii) * HWv];
        }
        float e0 = xl[4*i+0] - cv.x, e1 = xl[4*i+1] - cv.y;
        float e2 = xl[4*i+2] - cv.z, e3 = xl[4*i+3] - cv.w;
        nb = fmaf(e0, e0, nb); nb = fmaf(e1, e1, nb);
        nb = fmaf(e2, e2, nb); nb = fmaf(e3, e3, nb);
        nz[4*i+0] = nv.x; nz[4*i+1] = nv.y; nz[4*i+2] = nv.z; nz[4*i+3] = nv.w;
        nn += nv.x * nv.x + nv.y * nv.y + nv.z * nv.z + nv.w * nv.w;
    }
    // combine the two 32-dim partials (partner = adjacent lane)
    nb += __shfl_xor_sync(0xffffffffu, nb, 1);
    nn += __shfl_xor_sync(0xffffffffu, nn, 1);

    const float scale = sqrtf(nb) / sqrtf(nn) + EPSV;

    float* yo = out + (size_t)ebb * (Dv * HWv) + ehw;
    #pragma unroll
    for (int i = 0; i < 32; i++)
        yo[(size_t)(epar * 32 + i) * HWv] = fmaf(scale, nz[i], xl[i]);

    if (epar == 0) atomicAdd(&g_counts[myidx], 1u);

    // ---- last CTA computes perplexity ----
    __threadfence();
    __syncthreads();
    __shared__ unsigned int s_last;
    if (tid == 0) s_last = (atomicAdd(&g_ticket, 1u) == (unsigned)(GRID - 1)) ? 1u : 0u;
    __syncthreads();
    if (s_last) {
        float s = 0.f;
        for (int k = tid; k < Kv; k += THREADS) {
            float p = (float)g_counts[k] * (1.0f / (float)NROWS);
            s += p * logf(p + PERP_EPSV);
        }
        #pragma unroll
        for (int off = 16; off > 0; off >>= 1)
            s += __shfl_down_sync(0xffffffffu, s, off);
        float* ws = reinterpret_cast<float*>(sp + BST_OFF);
        if (lane == 0) ws[wid] = s;
        __syncthreads();
        if (tid < 16) {
            float v = ws[tid];
            #pragma unroll
            for (int off = 8; off > 0; off >>= 1)
                v += __shfl_down_sync(0xffffu, v, off);
            if (tid == 0) out[(size_t)NROWS * Dv] = expf(-v);
        }
    }
}

// ---------------------------------------------------------------------------
extern "C" void kernel_launch(void* const* d_in, const int* in_sizes, int n_in,
                              void* d_out, int out_size) {
    const float* inputs = (const float*)d_in[0];   // (32, 64, 32, 32)
    const float* cb     = (const float*)d_in[1];   // (1024, 64)
    const float* noise  = (const float*)d_in[2];   // (32768, 64)
    float*       out    = (float*)d_out;

    cudaFuncSetAttribute(nsvq_hmma_kernel,
                         cudaFuncAttributeMaxDynamicSharedMemorySize, SMEM_DYN);

    nsvq_prep_kernel<<<(Kv * 8) / 256, 256>>>(cb);
    nsvq_hmma_kernel<<<GRID, THREADS, SMEM_DYN>>>(inputs, cb, noise, out);
}

// round 8
// speedup vs baseline: 1.4121x; 1.4121x over previous
#include <cuda_runtime.h>
#include <cuda_bf16.h>
#include <cstdint>
#include <math.h>

// ---------------- problem constants ----------------
#define Dv      64
#define HWv     1024
#define NROWS   32768
#define Kv      1024
#define EPSV        1e-12f
#define PERP_EPSV   1e-10f

#define M_TILE   256                 // rows per CTA
#define THREADS  512                 // 16 warps: 2 codebook-halves x 8 row-warps
#define GRID     (NROWS / M_TILE)    // 128 CTAs -> single wave

// ---------------- SMEM layout (byte offsets into dynamic smem) ----------------
#define A_OFF    0                   // 256 x 64 bf16 (swizzled 128B rows) = 32KB
#define B_OFF    32768               // 1024 x 64 bf16 = 128KB
#define CN_OFF   163840              // 1024 fp32 norms = 4KB
#define BST_OFF  167936              // 2 x 256 fp32 best-dist
#define IDX_OFF  169984              // 2 x 256 int  best-idx
#define SMEM_DYN 172032

// ---------------- device scratch ----------------
__device__ __align__(16) float        g_cnorm[Kv];
__device__ unsigned int               g_counts[Kv];
__device__ unsigned int               g_ticket;
// codebook as bf16, PRE-SWIZZLED (16B-unit XOR by (row&7)<<4): linear cp.async.
__device__ __align__(16) unsigned char g_cb[Kv * Dv * 2];

// ---------------- helpers ----------------
__device__ __forceinline__ uint32_t smem_u32(const void* p) {
    uint32_t a;
    asm("{ .reg .u64 t; cvta.to.shared.u64 t, %1; cvt.u32.u64 %0, t; }"
        : "=r"(a) : "l"(p));
    return a;
}
#define SWZ(row, unit) ((((uint32_t)(row) * 128u) + (uint32_t)(unit) * 16u) ^ ((((uint32_t)(row)) & 7u) << 4))

__device__ __forceinline__ void ldsm4(uint32_t addr, uint32_t& r0, uint32_t& r1,
                                      uint32_t& r2, uint32_t& r3) {
    asm volatile("ldmatrix.sync.aligned.m8n8.x4.shared.b16 {%0,%1,%2,%3}, [%4];"
                 : "=r"(r0), "=r"(r1), "=r"(r2), "=r"(r3) : "r"(addr));
}
__device__ __forceinline__ void mma_bf16(float* d, const uint32_t* a, const uint32_t* b) {
    asm volatile(
        "mma.sync.aligned.m16n8k16.row.col.f32.bf16.bf16.f32 "
        "{%0,%1,%2,%3}, {%4,%5,%6,%7}, {%8,%9}, {%0,%1,%2,%3};"
        : "+f"(d[0]), "+f"(d[1]), "+f"(d[2]), "+f"(d[3])
        : "r"(a[0]), "r"(a[1]), "r"(a[2]), "r"(a[3]), "r"(b[0]), "r"(b[1]));
}
__device__ __forceinline__ void cp16(uint32_t saddr, const void* g) {
    asm volatile("cp.async.cg.shared.global [%0], [%1], 16;" :: "r"(saddr), "l"(g));
}
#define CP_COMMIT() asm volatile("cp.async.commit_group;" ::: "memory")
#define CP_WAIT0()  asm volatile("cp.async.wait_group 0;"  ::: "memory")

// ---------------------------------------------------------------------------
// prep: codebook bf16 convert (pre-swizzled) + exact fp32 norms + zero
// histogram + reset ticket. thread t -> (codebook k = t>>3, 16B-unit u = t&7).
// ---------------------------------------------------------------------------
__global__ void nsvq_prep_kernel(const float* __restrict__ cb) {
    const int t = blockIdx.x * blockDim.x + threadIdx.x;   // Kv*8 = 8192 threads
    const int k = t >> 3, u = t & 7;
    const float4* src = reinterpret_cast<const float4*>(cb + k * Dv + u * 8);
    float4 a = src[0], b = src[1];
    float v[8] = {a.x, a.y, a.z, a.w, b.x, b.y, b.z, b.w};

    float part = 0.f;
    unsigned short hs[8];
    #pragma unroll
    for (int i = 0; i < 8; i++) {
        part = fmaf(v[i], v[i], part);
        hs[i] = __bfloat16_as_ushort(__float2bfloat16(v[i]));
    }
    part += __shfl_xor_sync(0xffffffffu, part, 1);
    part += __shfl_xor_sync(0xffffffffu, part, 2);
    part += __shfl_xor_sync(0xffffffffu, part, 4);
    if (u == 0) g_cnorm[k] = part;

    uint4 ho;
    ho.x = (uint32_t)hs[0] | ((uint32_t)hs[1] << 16);
    ho.y = (uint32_t)hs[2] | ((uint32_t)hs[3] << 16);
    ho.z = (uint32_t)hs[4] | ((uint32_t)hs[5] << 16);
    ho.w = (uint32_t)hs[6] | ((uint32_t)hs[7] << 16);
    *reinterpret_cast<uint4*>(g_cb + SWZ(k, u)) = ho;

    if (t < Kv)  g_counts[t] = 0u;
    if (t == 0)  g_ticket = 0u;
}

// ---------------------------------------------------------------------------
// main: bf16 HMMA distance GEMM, split-K over codebook halves (16 warps),
// fused argmin merge + exact fp32 NSVQ epilogue (2 threads/row; x and noise
// re-reads are L1 hits: loaded once up-front) + last-CTA perplexity.
// ---------------------------------------------------------------------------
__global__ __launch_bounds__(THREADS, 1)
void nsvq_hmma_kernel(const float* __restrict__ inputs,
                      const float* __restrict__ cbf,
                      const float* __restrict__ noise,
                      float*       __restrict__ out)
{
    extern __shared__ char sp[];
    const uint32_t sbase = smem_u32(sp);

    const int tid   = threadIdx.x;
    const int wid   = tid >> 5;
    const int lane  = tid & 31;
    const int wslot = wid & 7;         // row-warp (32 rows)
    const int half  = wid >> 3;        // codebook half (0: k<512, 1: k>=512)

    // epilogue split: 2 threads per row, 32 dims each
    const int erow = tid >> 1;
    const int epar = tid & 1;
    const int en   = blockIdx.x * M_TILE + erow;     // global row
    const int ebb  = en >> 10;
    const int ehw  = en & 1023;
    const float* exin = inputs + (size_t)ebb * (Dv * HWv) + ehw + (size_t)(epar * 32) * HWv;
    const float4* enr = reinterpret_cast<const float4*>(noise + (size_t)en * Dv) + epar * 8;

    // ---- async copy: whole codebook + norms (bypasses L1 via .cg) ----
    {
        const char* gb = (const char*)g_cb;
        #pragma unroll
        for (int i = 0; i < 16; i++) {               // 512 thr x 16 x 16B = 128KB
            uint32_t o = ((uint32_t)tid + (uint32_t)i * 512u) * 16u;
            cp16(sbase + B_OFF + o, gb + o);
        }
        if (tid < 256)
            cp16(sbase + CN_OFF + (uint32_t)tid * 16u,
                 (const char*)g_cnorm + (size_t)tid * 16);
        CP_COMMIT();
    }

    // ---- load x half-row ONCE: feeds bf16 A-tile write, warms L1 for epilogue ----
    {
        float xl[32];
        #pragma unroll
        for (int i = 0; i < 32; i++) xl[i] = exin[(size_t)i * HWv];
        #pragma unroll
        for (int i = 0; i < 16; i++) {               // 16 bf16x2 words
            uint32_t off = SWZ(erow, epar * 4 + (i >> 2)) + (uint32_t)(i & 3) * 4u;
            unsigned short h0 = __bfloat16_as_ushort(__float2bfloat16(xl[2 * i]));
            unsigned short h1 = __bfloat16_as_ushort(__float2bfloat16(xl[2 * i + 1]));
            *reinterpret_cast<uint32_t*>(sp + A_OFF + off) = (uint32_t)h0 | ((uint32_t)h1 << 16);
        }
    }

    // ---- noise norm up-front (overlaps cp.async); nz re-read later from L1 ----
    float nn = 0.f;
    #pragma unroll
    for (int i = 0; i < 8; i++) {
        float4 nv = enr[i];
        nn += nv.x * nv.x + nv.y * nv.y + nv.z * nv.z + nv.w * nv.w;
    }
    nn += __shfl_xor_sync(0xffffffffu, nn, 1);       // partner = adjacent lane

    CP_WAIT0();
    __syncthreads();   // A + B + cn visible to all warps

    // ---- load A fragments (32 rows per row-warp) ----
    uint32_t ah[2][4][4];
    {
        const int arow = wslot * 32 + (lane & 7) + ((lane >> 3) & 1) * 8;
        const int aun  = (lane >> 4);
        #pragma unroll
        for (int mt = 0; mt < 2; mt++)
            #pragma unroll
            for (int kc = 0; kc < 4; kc++) {
                uint32_t ad = sbase + A_OFF + (uint32_t)SWZ(arow + mt * 16, kc * 2 + aun);
                ldsm4(ad, ah[mt][kc][0], ah[mt][kc][1], ah[mt][kc][2], ah[mt][kc][3]);
            }
    }

    float best[4] = {3.402823466e38f, 3.402823466e38f, 3.402823466e38f, 3.402823466e38f};
    int   bidx[4] = {0, 0, 0, 0};

    const int browq = (lane & 7) + ((lane >> 4) & 1) * 8;   // B ldmatrix row within n16
    const int bunq  = (lane >> 3) & 1;                       // B k-unit parity
    const float* cn = reinterpret_cast<const float*>(sp + CN_OFF);

    // strength-reduced swizzled B base: group step = 16 rows (0 mod 8) -> XOR const
    const uint32_t xorv = ((uint32_t)(browq & 7)) << 4;
    uint32_t bbase = sbase + B_OFF + (uint32_t)(half * 512 + browq) * 128u;
    uint32_t ukc[4];
    #pragma unroll
    for (int kc = 0; kc < 4; kc++)
        ukc[kc] = (((uint32_t)(kc * 2 + bunq)) * 16u) ^ xorv;

    #pragma unroll 2
    for (int g = 0; g < 32; g++) {                    // 32 n-groups of 16 per half
        float acc[2][2][4];
        #pragma unroll
        for (int mt = 0; mt < 2; mt++)
            #pragma unroll
            for (int nt = 0; nt < 2; nt++)
                #pragma unroll
                for (int j = 0; j < 4; j++) acc[mt][nt][j] = 0.f;

        #pragma unroll
        for (int kc = 0; kc < 4; kc++) {
            uint32_t bh[4];
            ldsm4(bbase + ukc[kc], bh[0], bh[1], bh[2], bh[3]);
            #pragma unroll
            for (int mt = 0; mt < 2; mt++) {
                mma_bf16(acc[mt][0], ah[mt][kc], bh + 0);
                mma_bf16(acc[mt][1], ah[mt][kc], bh + 2);
            }
        }
        bbase += 16u * 128u;

        const int cb0 = half * 512 + g * 16 + 2 * (lane & 3);
        float cnl[4];
        {
            float2 p0 = *reinterpret_cast<const float2*>(cn + cb0);
            float2 p1 = *reinterpret_cast<const float2*>(cn + cb0 + 8);
            cnl[0] = p0.x; cnl[1] = p0.y; cnl[2] = p1.x; cnl[3] = p1.y;
        }
        #pragma unroll
        for (int mt = 0; mt < 2; mt++)
            #pragma unroll
            for (int nt = 0; nt < 2; nt++)
                #pragma unroll
                for (int j = 0; j < 4; j++) {
                    float dist = fmaf(-2.f, acc[mt][nt][j], cnl[nt * 2 + (j & 1)]);
                    int   kk   = cb0 + nt * 8 + (j & 1);
                    int   s    = mt * 2 + (j >> 1);
                    if (dist < best[s]) { best[s] = dist; bidx[s] = kk; }
                }
    }

    // ---- quad butterfly reduce (lanes sharing the same rows) ----
    #pragma unroll
    for (int s = 0; s < 4; s++) {
        #pragma unroll
        for (int d = 1; d <= 2; d <<= 1) {
            float od = __shfl_xor_sync(0xffffffffu, best[s], d);
            int   oi = __shfl_xor_sync(0xffffffffu, bidx[s], d);
            if (od < best[s] || (od == best[s] && oi < bidx[s])) { best[s] = od; bidx[s] = oi; }
        }
    }
    {
        float* sbst = reinterpret_cast<float*>(sp + BST_OFF) + half * 256;
        int*   sidx = reinterpret_cast<int*>(sp + IDX_OFF)  + half * 256;
        int r = wslot * 32 + (lane >> 2) + (lane & 3) * 8;
        sbst[r] = best[lane & 3];
        sidx[r] = bidx[lane & 3];
    }
    __syncthreads();

    // ---- merge halves (half-0 indices < half-1: tie -> half 0 = jnp rule) ----
    int myidx;
    {
        const float* sbst = reinterpret_cast<const float*>(sp + BST_OFF);
        const int*   sidx = reinterpret_cast<const int*>(sp + IDX_OFF);
        float d0 = sbst[erow], d1 = sbst[256 + erow];
        myidx = (d1 < d0) ? sidx[256 + erow] : sidx[erow];
    }

    // ---- exact fp32 NSVQ epilogue: x / noise re-reads hit L1 ----
    const float4* cbest4 = reinterpret_cast<const float4*>(cbf + (size_t)myidx * Dv) + epar * 8;

    float xl[32], nz[32];
    float nb = 0.f;
    #pragma unroll
    for (int i = 0; i < 8; i++) {
        float4 cv = cbest4[i];
        float4 nv = enr[i];
        #pragma unroll
        for (int j = 0; j < 4; j++) xl[4 * i + j] = exin[(size_t)(4 * i + j) * HWv];
        float e0 = xl[4*i+0] - cv.x, e1 = xl[4*i+1] - cv.y;
        float e2 = xl[4*i+2] - cv.z, e3 = xl[4*i+3] - cv.w;
        nb = fmaf(e0, e0, nb); nb = fmaf(e1, e1, nb);
        nb = fmaf(e2, e2, nb); nb = fmaf(e3, e3, nb);
        nz[4*i+0] = nv.x; nz[4*i+1] = nv.y; nz[4*i+2] = nv.z; nz[4*i+3] = nv.w;
    }
    nb += __shfl_xor_sync(0xffffffffu, nb, 1);

    const float scale = sqrtf(nb) / sqrtf(nn) + EPSV;

    float* yo = out + (size_t)ebb * (Dv * HWv) + ehw + (size_t)(epar * 32) * HWv;
    #pragma unroll
    for (int i = 0; i < 32; i++)
        yo[(size_t)i * HWv] = fmaf(scale, nz[i], xl[i]);

    if (epar == 0) atomicAdd(&g_counts[myidx], 1u);

    // ---- last CTA computes perplexity ----
    __threadfence();
    __syncthreads();
    __shared__ unsigned int s_last;
    if (tid == 0) s_last = (atomicAdd(&g_ticket, 1u) == (unsigned)(GRID - 1)) ? 1u : 0u;
    __syncthreads();
    if (s_last) {
        float s = 0.f;
        for (int k = tid; k < Kv; k += THREADS) {
            float p = (float)g_counts[k] * (1.0f / (float)NROWS);
            s += p * logf(p + PERP_EPSV);
        }
        #pragma unroll
        for (int off = 16; off > 0; off >>= 1)
            s += __shfl_down_sync(0xffffffffu, s, off);
        float* ws = reinterpret_cast<float*>(sp + BST_OFF);
        if (lane == 0) ws[wid] = s;
        __syncthreads();
        if (tid < 16) {
            float v = ws[tid];
            #pragma unroll
            for (int off = 8; off > 0; off >>= 1)
                v += __shfl_down_sync(0xffffu, v, off);
            if (tid == 0) out[(size_t)NROWS * Dv] = expf(-v);
        }
    }
}

// ---------------------------------------------------------------------------
extern "C" void kernel_launch(void* const* d_in, const int* in_sizes, int n_in,
                              void* d_out, int out_size) {
    const float* inputs = (const float*)d_in[0];   // (32, 64, 32, 32)
    const float* cb     = (const float*)d_in[1];   // (1024, 64)
    const float* noise  = (const float*)d_in[2];   // (32768, 64)
    float*       out    = (float*)d_out;

    cudaFuncSetAttribute(nsvq_hmma_kernel,
                         cudaFuncAttributeMaxDynamicSharedMemorySize, SMEM_DYN);

    nsvq_prep_kernel<<<(Kv * 8) / 256, 256>>>(cb);
    nsvq_hmma_kernel<<<GRID, THREADS, SMEM_DYN>>>(inputs, cb, noise, out);
}

// round 10
// speedup vs baseline: 1.5005x; 1.0626x over previous
#include <cuda_runtime.h>
#include <cuda_bf16.h>
#include <cstdint>
#include <math.h>

// ---------------- problem constants ----------------
#define Dv      64
#define HWv     1024
#define NROWS   32768
#define Kv      1024
#define EPSV        1e-12f
#define PERP_EPSV   1e-10f

#define M_TILE   256                 // rows per CTA
#define THREADS  512                 // 16 warps: 2 codebook-halves x 8 row-warps
#define GRID     (NROWS / M_TILE)    // 128 CTAs -> single wave

// ---------------- SMEM layout (byte offsets into dynamic smem) ----------------
#define A_OFF    0                   // 256 x 64 bf16 (swizzled 128B rows) = 32KB
#define B_OFF    32768               // 1024 x 64 bf16 = 128KB
#define CN_OFF   163840              // 1024 fp32 norms = 4KB
#define BST_OFF  167936              // 2 x 256 fp32 best-dist
#define IDX_OFF  169984              // 2 x 256 int  best-idx
#define SMEM_DYN 172032

// ---------------- device scratch ----------------
__device__ __align__(16) float        g_cnorm[Kv];
__device__ unsigned int               g_counts[Kv];
__device__ unsigned int               g_ticket;
// codebook as bf16, PRE-SWIZZLED (16B-unit XOR by (row&7)<<4): linear cp.async.
__device__ __align__(16) unsigned char g_cb[Kv * Dv * 2];

// ---------------- helpers ----------------
__device__ __forceinline__ uint32_t smem_u32(const void* p) {
    uint32_t a;
    asm("{ .reg .u64 t; cvta.to.shared.u64 t, %1; cvt.u32.u64 %0, t; }"
        : "=r"(a) : "l"(p));
    return a;
}
#define SWZ(row, unit) ((((uint32_t)(row) * 128u) + (uint32_t)(unit) * 16u) ^ ((((uint32_t)(row)) & 7u) << 4))

__device__ __forceinline__ void ldsm4(uint32_t addr, uint32_t& r0, uint32_t& r1,
                                      uint32_t& r2, uint32_t& r3) {
    asm volatile("ldmatrix.sync.aligned.m8n8.x4.shared.b16 {%0,%1,%2,%3}, [%4];"
                 : "=r"(r0), "=r"(r1), "=r"(r2), "=r"(r3) : "r"(addr));
}
__device__ __forceinline__ void mma_bf16(float* d, const uint32_t* a, const uint32_t* b) {
    asm volatile(
        "mma.sync.aligned.m16n8k16.row.col.f32.bf16.bf16.f32 "
        "{%0,%1,%2,%3}, {%4,%5,%6,%7}, {%8,%9}, {%0,%1,%2,%3};"
        : "+f"(d[0]), "+f"(d[1]), "+f"(d[2]), "+f"(d[3])
        : "r"(a[0]), "r"(a[1]), "r"(a[2]), "r"(a[3]), "r"(b[0]), "r"(b[1]));
}
__device__ __forceinline__ void cp16(uint32_t saddr, const void* g) {
    asm volatile("cp.async.cg.shared.global [%0], [%1], 16;" :: "r"(saddr), "l"(g));
}
#define CP_COMMIT() asm volatile("cp.async.commit_group;" ::: "memory")
#define CP_WAIT0()  asm volatile("cp.async.wait_group 0;"  ::: "memory")

// embed 7-bit code into low mantissa bits (dists are positive: float order = bit order)
__device__ __forceinline__ float embed7(float d, uint32_t code) {
    return __uint_as_float((__float_as_uint(d) & 0xFFFFFF80u) | code);
}

// ---------------------------------------------------------------------------
// prep: codebook bf16 convert (pre-swizzled) + exact fp32 norms + zero
// histogram + reset ticket. thread t -> (codebook k = t>>3, 16B-unit u = t&7).
// ---------------------------------------------------------------------------
__global__ void nsvq_prep_kernel(const float* __restrict__ cb) {
    const int t = blockIdx.x * blockDim.x + threadIdx.x;   // Kv*8 = 8192 threads
    const int k = t >> 3, u = t & 7;
    const float4* src = reinterpret_cast<const float4*>(cb + k * Dv + u * 8);
    float4 a = src[0], b = src[1];
    float v[8] = {a.x, a.y, a.z, a.w, b.x, b.y, b.z, b.w};

    float part = 0.f;
    unsigned short hs[8];
    #pragma unroll
    for (int i = 0; i < 8; i++) {
        part = fmaf(v[i], v[i], part);
        hs[i] = __bfloat16_as_ushort(__float2bfloat16(v[i]));
    }
    part += __shfl_xor_sync(0xffffffffu, part, 1);
    part += __shfl_xor_sync(0xffffffffu, part, 2);
    part += __shfl_xor_sync(0xffffffffu, part, 4);
    if (u == 0) g_cnorm[k] = part;

    uint4 ho;
    ho.x = (uint32_t)hs[0] | ((uint32_t)hs[1] << 16);
    ho.y = (uint32_t)hs[2] | ((uint32_t)hs[3] << 16);
    ho.z = (uint32_t)hs[4] | ((uint32_t)hs[5] << 16);
    ho.w = (uint32_t)hs[6] | ((uint32_t)hs[7] << 16);
    *reinterpret_cast<uint4*>(g_cb + SWZ(k, u)) = ho;

    if (t < Kv)  g_counts[t] = 0u;
    if (t == 0)  g_ticket = 0u;
}

// ---------------------------------------------------------------------------
// main: bf16 HMMA distance GEMM, split-K over codebook halves (16 warps),
// argmin via FMNMX trees with mantissa-embedded (group, elem) payload,
// exact fp32 NSVQ epilogue (2 threads/row, L1-warmed) + last-CTA perplexity.
// ---------------------------------------------------------------------------
__global__ __launch_bounds__(THREADS, 1)
void nsvq_hmma_kernel(const float* __restrict__ inputs,
                      const float* __restrict__ cbf,
                      const float* __restrict__ noise,
                      float*       __restrict__ out)
{
    extern __shared__ char sp[];
    const uint32_t sbase = smem_u32(sp);

    const int tid   = threadIdx.x;
    const int wid   = tid >> 5;
    const int lane  = tid & 31;
    const int wslot = wid & 7;         // row-warp (32 rows)
    const int half  = wid >> 3;        // codebook half (0: k<512, 1: k>=512)

    // epilogue split: 2 threads per row, 32 dims each
    const int erow = tid >> 1;
    const int epar = tid & 1;
    const int en   = blockIdx.x * M_TILE + erow;     // global row
    const int ebb  = en >> 10;
    const int ehw  = en & 1023;
    const float* exin = inputs + (size_t)ebb * (Dv * HWv) + ehw + (size_t)(epar * 32) * HWv;
    const float4* enr = reinterpret_cast<const float4*>(noise + (size_t)en * Dv) + epar * 8;

    // ---- async copy: whole codebook + norms (bypasses L1 via .cg) ----
    {
        const char* gb = (const char*)g_cb;
        #pragma unroll
        for (int i = 0; i < 16; i++) {               // 512 thr x 16 x 16B = 128KB
            uint32_t o = ((uint32_t)tid + (uint32_t)i * 512u) * 16u;
            cp16(sbase + B_OFF + o, gb + o);
        }
        if (tid < 256)
            cp16(sbase + CN_OFF + (uint32_t)tid * 16u,
                 (const char*)g_cnorm + (size_t)tid * 16);
        CP_COMMIT();
    }

    // ---- load x half-row ONCE: feeds bf16 A-tile write, warms L1 for epilogue ----
    {
        float xl[32];
        #pragma unroll
        for (int i = 0; i < 32; i++) xl[i] = exin[(size_t)i * HWv];
        #pragma unroll
        for (int i = 0; i < 16; i++) {               // 16 bf16x2 words
            uint32_t off = SWZ(erow, epar * 4 + (i >> 2)) + (uint32_t)(i & 3) * 4u;
            unsigned short h0 = __bfloat16_as_ushort(__float2bfloat16(xl[2 * i]));
            unsigned short h1 = __bfloat16_as_ushort(__float2bfloat16(xl[2 * i + 1]));
            *reinterpret_cast<uint32_t*>(sp + A_OFF + off) = (uint32_t)h0 | ((uint32_t)h1 << 16);
        }
    }

    // ---- noise norm up-front (overlaps cp.async); nz re-read later from L1 ----
    float nn = 0.f;
    #pragma unroll
    for (int i = 0; i < 8; i++) {
        float4 nv = enr[i];
        nn += nv.x * nv.x + nv.y * nv.y + nv.z * nv.z + nv.w * nv.w;
    }
    nn += __shfl_xor_sync(0xffffffffu, nn, 1);       // partner = adjacent lane

    CP_WAIT0();
    __syncthreads();   // A + B + cn visible to all warps

    // ---- load A fragments (32 rows per row-warp) ----
    uint32_t ah[2][4][4];
    {
        const int arow = wslot * 32 + (lane & 7) + ((lane >> 3) & 1) * 8;
        const int aun  = (lane >> 4);
        #pragma unroll
        for (int mt = 0; mt < 2; mt++)
            #pragma unroll
            for (int kc = 0; kc < 4; kc++) {
                uint32_t ad = sbase + A_OFF + (uint32_t)SWZ(arow + mt * 16, kc * 2 + aun);
                ldsm4(ad, ah[mt][kc][0], ah[mt][kc][1], ah[mt][kc][2], ah[mt][kc][3]);
            }
    }

    // per row-slot: best embedded dist (payload = g<<2 | elem in low 7 bits)
    float best[4] = {3.402823466e38f, 3.402823466e38f, 3.402823466e38f, 3.402823466e38f};

    const int browq = (lane & 7) + ((lane >> 4) & 1) * 8;   // B ldmatrix row within n16
    const int bunq  = (lane >> 3) & 1;                       // B k-unit parity
    const float* cn = reinterpret_cast<const float*>(sp + CN_OFF);

    // strength-reduced swizzled B base: group step = 16 rows (0 mod 8) -> XOR const
    const uint32_t xorv = ((uint32_t)(browq & 7)) << 4;
    uint32_t bbase = sbase + B_OFF + (uint32_t)(half * 512 + browq) * 128u;
    uint32_t ukc[4];
    #pragma unroll
    for (int kc = 0; kc < 4; kc++)
        ukc[kc] = (((uint32_t)(kc * 2 + bunq)) * 16u) ^ xorv;

    #pragma unroll 2
    for (int g = 0; g < 32; g++) {                    // 32 n-groups of 16 per half
        float acc[2][2][4];
        #pragma unroll
        for (int mt = 0; mt < 2; mt++)
            #pragma unroll
            for (int nt = 0; nt < 2; nt++)
                #pragma unroll
                for (int j = 0; j < 4; j++) acc[mt][nt][j] = 0.f;

        #pragma unroll
        for (int kc = 0; kc < 4; kc++) {
            uint32_t bh[4];
            ldsm4(bbase + ukc[kc], bh[0], bh[1], bh[2], bh[3]);
            #pragma unroll
            for (int mt = 0; mt < 2; mt++) {
                mma_bf16(acc[mt][0], ah[mt][kc], bh + 0);
                mma_bf16(acc[mt][1], ah[mt][kc], bh + 2);
            }
        }
        bbase += 16u * 128u;

        const int cb0 = half * 512 + g * 16 + 2 * (lane & 3);
        float cnl[4];
        {
            float2 p0 = *reinterpret_cast<const float2*>(cn + cb0);
            float2 p1 = *reinterpret_cast<const float2*>(cn + cb0 + 8);
            cnl[0] = p0.x; cnl[1] = p0.y; cnl[2] = p1.x; cnl[3] = p1.y;
        }
        const uint32_t g4 = (uint32_t)g << 2;
        // elem codes 0,1,2,3 in increasing column order {+0,+1,+8,+9}:
        // first-occurrence preserved through pure fmin chains.
        #pragma unroll
        for (int s = 0; s < 4; s++) {
            const int mt = s >> 1, jb = (s & 1) * 2;
            float e0 = embed7(fmaf(-2.f, acc[mt][0][jb],     cnl[0]), g4 | 0u);
            float e1 = embed7(fmaf(-2.f, acc[mt][0][jb + 1], cnl[1]), g4 | 1u);
            float e2 = embed7(fmaf(-2.f, acc[mt][1][jb],     cnl[2]), g4 | 2u);
            float e3 = embed7(fmaf(-2.f, acc[mt][1][jb + 1], cnl[3]), g4 | 3u);
            best[s] = fminf(best[s], fminf(fminf(e0, e1), fminf(e2, e3)));
        }
    }

    // ---- decode payload -> codebook index (lane&3 re-attached here) ----
    int bidx[4];
    #pragma unroll
    for (int s = 0; s < 4; s++) {
        uint32_t b = __float_as_uint(best[s]);
        int g  = (int)((b >> 2) & 31u);
        int el = (int)(b & 3u);
        bidx[s] = half * 512 + g * 16 + 2 * (lane & 3) + (el >> 1) * 8 + (el & 1);
    }

    // ---- quad butterfly reduce (lanes sharing the same rows) ----
    #pragma unroll
    for (int s = 0; s < 4; s++) {
        #pragma unroll
        for (int d = 1; d <= 2; d <<= 1) {
            float od = __shfl_xor_sync(0xffffffffu, best[s], d);
            int   oi = __shfl_xor_sync(0xffffffffu, bidx[s], d);
            if (od < best[s] || (od == best[s] && oi < bidx[s])) { best[s] = od; bidx[s] = oi; }
        }
    }
    {
        float* sbst = reinterpret_cast<float*>(sp + BST_OFF) + half * 256;
        int*   sidx = reinterpret_cast<int*>(sp + IDX_OFF)  + half * 256;
        int r = wslot * 32 + (lane >> 2) + (lane & 3) * 8;
        sbst[r] = best[lane & 3];
        sidx[r] = bidx[lane & 3];
    }
    __syncthreads();

    // ---- merge halves (half-0 indices < half-1: tie -> half 0 = jnp rule) ----
    int myidx;
    {
        const float* sbst = reinterpret_cast<const float*>(sp + BST_OFF);
        const int*   sidx = reinterpret_cast<const int*>(sp + IDX_OFF);
        float d0 = sbst[erow], d1 = sbst[256 + erow];
        myidx = (d1 < d0) ? sidx[256 + erow] : sidx[erow];
    }

    // ---- exact fp32 NSVQ epilogue: x / noise re-reads hit L1 ----
    const float4* cbest4 = reinterpret_cast<const float4*>(cbf + (size_t)myidx * Dv) + epar * 8;

    float xl[32], nz[32];
    float nb = 0.f;
    #pragma unroll
    for (int i = 0; i < 8; i++) {
        float4 cv = cbest4[i];
        float4 nv = enr[i];
        #pragma unroll
        for (int j = 0; j < 4; j++) xl[4 * i + j] = exin[(size_t)(4 * i + j) * HWv];
        float e0 = xl[4*i+0] - cv.x, e1 = xl[4*i+1] - cv.y;
        float e2 = xl[4*i+2] - cv.z, e3 = xl[4*i+3] - cv.w;
        nb = fmaf(e0, e0, nb); nb = fmaf(e1, e1, nb);
        nb = fmaf(e2, e2, nb); nb = fmaf(e3, e3, nb);
        nz[4*i+0] = nv.x; nz[4*i+1] = nv.y; nz[4*i+2] = nv.z; nz[4*i+3] = nv.w;
    }
    nb += __shfl_xor_sync(0xffffffffu, nb, 1);

    const float scale = sqrtf(nb) / sqrtf(nn) + EPSV;

    float* yo = out + (size_t)ebb * (Dv * HWv) + ehw + (size_t)(epar * 32) * HWv;
    #pragma unroll
    for (int i = 0; i < 32; i++)
        yo[(size_t)i * HWv] = fmaf(scale, nz[i], xl[i]);

    if (epar == 0) atomicAdd(&g_counts[myidx], 1u);

    // ---- last CTA computes perplexity ----
    __threadfence();
    __syncthreads();
    __shared__ unsigned int s_last;
    if (tid == 0) s_last = (atomicAdd(&g_ticket, 1u) == (unsigned)(GRID - 1)) ? 1u : 0u;
    __syncthreads();
    if (s_last) {
        float s = 0.f;
        for (int k = tid; k < Kv; k += THREADS) {
            float p = (float)g_counts[k] * (1.0f / (float)NROWS);
            s += p * logf(p + PERP_EPSV);
        }
        #pragma unroll
        for (int off = 16; off > 0; off >>= 1)
            s += __shfl_down_sync(0xffffffffu, s, off);
        float* ws = reinterpret_cast<float*>(sp + BST_OFF);
        if (lane == 0) ws[wid] = s;
        __syncthreads();
        if (tid < 16) {
            float v = ws[tid];
            #pragma unroll
            for (int off = 8; off > 0; off >>= 1)
                v += __shfl_down_sync(0xffffu, v, off);
            if (tid == 0) out[(size_t)NROWS * Dv] = expf(-v);
        }
    }
}

// ---------------------------------------------------------------------------
extern "C" void kernel_launch(void* const* d_in, const int* in_sizes, int n_in,
                              void* d_out, int out_size) {
    const float* inputs = (const float*)d_in[0];   // (32, 64, 32, 32)
    const float* cb     = (const float*)d_in[1];   // (1024, 64)
    const float* noise  = (const float*)d_in[2];   // (32768, 64)
    float*       out    = (float*)d_out;

    cudaFuncSetAttribute(nsvq_hmma_kernel,
                         cudaFuncAttributeMaxDynamicSharedMemorySize, SMEM_DYN);

    nsvq_prep_kernel<<<(Kv * 8) / 256, 256>>>(cb);
    nsvq_hmma_kernel<<<GRID, THREADS, SMEM_DYN>>>(inputs, cb, noise, out);
}